// round 1
// baseline (speedup 1.0000x reference)
#include <cuda_runtime.h>

#define NN   100000
#define EE   3200000
#define FIN  512
#define HH   64
#define CC   8

// ---------------- scratch (device globals; no runtime allocation) ----------
__device__ float g_h1[NN * HH];       // x @ W1
__device__ float g_t2[NN * CC];       // relu(agg1 + b1) @ W2
__device__ int   g_deg[NN];           // edge-only in-degree
__device__ float g_dinv[NN];          // rsqrt(deg + 1)  (self-loop included)
__device__ int   g_rowptr[NN + 1];
__device__ int   g_cursor[NN];
__device__ int   g_col[EE];           // CSR col (src) per dst
__device__ int   g_bsum[512];
__device__ int   g_boff[512];

// ---------------- packed f32x2 helpers -------------------------------------
__device__ __forceinline__ unsigned long long pk2(float a, float b) {
    unsigned long long r;
    asm("mov.b64 %0, {%1,%2};" : "=l"(r) : "f"(a), "f"(b));
    return r;
}
__device__ __forceinline__ void fma2(unsigned long long& c,
                                     unsigned long long a,
                                     unsigned long long b) {
    asm("fma.rn.f32x2 %0, %1, %2, %3;" : "=l"(c) : "l"(a), "l"(b), "l"(c));
}
struct __align__(16) ULL2 { unsigned long long x, y; };

// ---------------- CSR construction ------------------------------------------
__global__ void k_zero_deg(int n) {
    int i = blockIdx.x * blockDim.x + threadIdx.x;
    if (i < n) g_deg[i] = 0;
}

__global__ void k_hist(const int* __restrict__ dst, int e) {
    int i = blockIdx.x * blockDim.x + threadIdx.x;
    if (i < e) atomicAdd(&g_deg[dst[i]], 1);
}

__global__ void k_bsum(int n) {
    __shared__ int s[256];
    int t = threadIdx.x;
    int i = blockIdx.x * 256 + t;
    s[t] = (i < n) ? g_deg[i] : 0;
    __syncthreads();
    for (int o = 128; o > 0; o >>= 1) {
        if (t < o) s[t] += s[t + o];
        __syncthreads();
    }
    if (t == 0) g_bsum[blockIdx.x] = s[0];
}

__global__ void k_scan_bsum(int nb) {
    __shared__ int s[512];
    int t = threadIdx.x;
    int v = (t < nb) ? g_bsum[t] : 0;
    s[t] = v;
    __syncthreads();
    for (int o = 1; o < 512; o <<= 1) {
        int a = (t >= o) ? s[t - o] : 0;
        __syncthreads();
        s[t] += a;
        __syncthreads();
    }
    if (t < nb) g_boff[t] = s[t] - v;   // exclusive
}

__global__ void k_scan_final(int n, int e) {
    __shared__ int s[256];
    int t = threadIdx.x;
    int i = blockIdx.x * 256 + t;
    int v = (i < n) ? g_deg[i] : 0;
    s[t] = v;
    __syncthreads();
    for (int o = 1; o < 256; o <<= 1) {
        int a = (t >= o) ? s[t - o] : 0;
        __syncthreads();
        s[t] += a;
        __syncthreads();
    }
    if (i < n) {
        int excl = g_boff[blockIdx.x] + s[t] - v;
        g_rowptr[i] = excl;
        g_cursor[i] = excl;
        g_dinv[i]   = rsqrtf((float)(v + 1));
    }
    if (i == 0) g_rowptr[n] = e;
}

__global__ void k_scatter(const int* __restrict__ src,
                          const int* __restrict__ dst, int e) {
    int i = blockIdx.x * blockDim.x + threadIdx.x;
    if (i < e) {
        int d   = dst[i];
        int pos = atomicAdd(&g_cursor[d], 1);
        g_col[pos] = src[i];
    }
}

// ---------------- GEMM1: h1 = x @ W1 (fp32 via f32x2 FFMA) ------------------
#define BM 128
#define BN 64
#define BK 16

__global__ __launch_bounds__(256) void k_gemm1(const float* __restrict__ x,
                                               const float* __restrict__ W1,
                                               int n) {
    __shared__ float xs[BK][BM + 4];   // [k][row], stride multiple of 16B
    __shared__ float ws[BK][BN];       // [k][col]

    int tid   = threadIdx.x;
    int tx    = tid & 7;               // col group 0..7
    int ty    = tid >> 3;              // row group 0..31
    int mBase = blockIdx.x * BM;
    int r0    = ty * 4;
    int c0    = tx * 8;

    unsigned long long acc[4][4];
#pragma unroll
    for (int r = 0; r < 4; r++)
#pragma unroll
        for (int c = 0; c < 4; c++) acc[r][c] = 0ull;

    for (int kb = 0; kb < FIN; kb += BK) {
        // x tile: 128 rows x 16 k, 512 float4s
#pragma unroll
        for (int l = 0; l < 2; l++) {
            int id  = tid + l * 256;
            int row = id >> 2;
            int kq  = (id & 3) * 4;
            float4 v = make_float4(0.f, 0.f, 0.f, 0.f);
            int gr = mBase + row;
            if (gr < n)
                v = *(const float4*)&x[(size_t)gr * FIN + kb + kq];
            xs[kq + 0][row] = v.x;
            xs[kq + 1][row] = v.y;
            xs[kq + 2][row] = v.z;
            xs[kq + 3][row] = v.w;
        }
        // W tile: 16 x 64 floats, 256 float4s
        {
            int krow = tid >> 4;
            int c4   = (tid & 15) * 4;
            *(float4*)&ws[krow][c4] =
                *(const float4*)&W1[(size_t)(kb + krow) * HH + c4];
        }
        __syncthreads();

#pragma unroll
        for (int k = 0; k < BK; k++) {
            float4 xa = *(float4*)&xs[k][r0];
            ULL2 w0 = *(ULL2*)&ws[k][c0];
            ULL2 w1 = *(ULL2*)&ws[k][c0 + 4];
            unsigned long long a0 = pk2(xa.x, xa.x);
            unsigned long long a1 = pk2(xa.y, xa.y);
            unsigned long long a2 = pk2(xa.z, xa.z);
            unsigned long long a3 = pk2(xa.w, xa.w);
            fma2(acc[0][0], a0, w0.x); fma2(acc[0][1], a0, w0.y);
            fma2(acc[0][2], a0, w1.x); fma2(acc[0][3], a0, w1.y);
            fma2(acc[1][0], a1, w0.x); fma2(acc[1][1], a1, w0.y);
            fma2(acc[1][2], a1, w1.x); fma2(acc[1][3], a1, w1.y);
            fma2(acc[2][0], a2, w0.x); fma2(acc[2][1], a2, w0.y);
            fma2(acc[2][2], a2, w1.x); fma2(acc[2][3], a2, w1.y);
            fma2(acc[3][0], a3, w0.x); fma2(acc[3][1], a3, w0.y);
            fma2(acc[3][2], a3, w1.x); fma2(acc[3][3], a3, w1.y);
        }
        __syncthreads();
    }

#pragma unroll
    for (int r = 0; r < 4; r++) {
        int gr = mBase + r0 + r;
        if (gr < n) {
            float2 f0 = *(float2*)&acc[r][0];
            float2 f1 = *(float2*)&acc[r][1];
            float2 f2 = *(float2*)&acc[r][2];
            float2 f3 = *(float2*)&acc[r][3];
            *(float4*)&g_h1[(size_t)gr * HH + c0] =
                make_float4(f0.x, f0.y, f1.x, f1.y);
            *(float4*)&g_h1[(size_t)gr * HH + c0 + 4] =
                make_float4(f2.x, f2.y, f3.x, f3.y);
        }
    }
}

// ---------------- layer-1 aggregate + bias + ReLU + @W2 ---------------------
// one warp per dst node; lane t owns features (2t, 2t+1)
__global__ __launch_bounds__(256) void k_agg1(const float* __restrict__ b1,
                                              const float* __restrict__ W2,
                                              int n) {
    __shared__ float b1s[HH];
    __shared__ float w2t[CC * HH];   // transposed: [c][k]

    int tid = threadIdx.x;
    if (tid < HH) b1s[tid] = b1[tid];
    for (int i = tid; i < CC * HH; i += 256) {
        int c = i >> 6, k = i & 63;
        w2t[i] = W2[k * CC + c];
    }
    __syncthreads();

    int warp = tid >> 5, lane = tid & 31;
    int d = blockIdx.x * 8 + warp;
    if (d >= n) return;

    float dd = g_dinv[d];
    const float2* h2 = (const float2*)g_h1;

    float2 self = h2[(size_t)d * 32 + lane];
    float2 acc;
    acc.x = self.x * dd * dd;
    acc.y = self.y * dd * dd;

    int e   = g_rowptr[d];
    int end = g_rowptr[d + 1];
    for (; e + 2 <= end; e += 2) {
        int s0 = g_col[e], s1 = g_col[e + 1];
        float w0 = g_dinv[s0] * dd;
        float w1 = g_dinv[s1] * dd;
        float2 v0 = h2[(size_t)s0 * 32 + lane];
        float2 v1 = h2[(size_t)s1 * 32 + lane];
        acc.x += w0 * v0.x + w1 * v1.x;
        acc.y += w0 * v0.y + w1 * v1.y;
    }
    if (e < end) {
        int s = g_col[e];
        float w = g_dinv[s] * dd;
        float2 v = h2[(size_t)s * 32 + lane];
        acc.x += w * v.x;
        acc.y += w * v.y;
    }

    float hx = fmaxf(acc.x + b1s[2 * lane], 0.f);
    float hy = fmaxf(acc.y + b1s[2 * lane + 1], 0.f);

    float pw[8];
#pragma unroll
    for (int c = 0; c < 8; c++) {
        float2 q = *(float2*)&w2t[c * HH + 2 * lane];
        pw[c] = hx * q.x + hy * q.y;
    }
#pragma unroll
    for (int c = 0; c < 8; c++) {
        pw[c] += __shfl_down_sync(0xffffffffu, pw[c], 16);
        pw[c] += __shfl_down_sync(0xffffffffu, pw[c], 8);
        pw[c] += __shfl_down_sync(0xffffffffu, pw[c], 4);
        pw[c] += __shfl_down_sync(0xffffffffu, pw[c], 2);
        pw[c] += __shfl_down_sync(0xffffffffu, pw[c], 1);
    }
    if (lane == 0) {
        *(float4*)&g_t2[(size_t)d * CC]     = make_float4(pw[0], pw[1], pw[2], pw[3]);
        *(float4*)&g_t2[(size_t)d * CC + 4] = make_float4(pw[4], pw[5], pw[6], pw[7]);
    }
}

// ---------------- layer-2 aggregate + b2 -> out ------------------------------
// one warp per dst; lane = j*8 + c handles edge-slot j (4 edges/iter), feature c
__global__ __launch_bounds__(256) void k_agg2(const float* __restrict__ b2,
                                              float* __restrict__ out, int n) {
    int tid  = threadIdx.x;
    int warp = tid >> 5, lane = tid & 31;
    int d = blockIdx.x * 8 + warp;
    if (d >= n) return;
    int j = lane >> 3, c = lane & 7;

    float dd  = g_dinv[d];
    int beg   = g_rowptr[d];
    int end   = g_rowptr[d + 1];
    float acc = 0.f;
    for (int e = beg + j; e < end; e += 4) {
        int s = g_col[e];
        acc += g_dinv[s] * g_t2[(size_t)s * CC + c];
    }
    acc += __shfl_down_sync(0xffffffffu, acc, 16);
    acc += __shfl_down_sync(0xffffffffu, acc, 8);
    if (j == 0) {
        float r = dd * (acc + dd * g_t2[(size_t)d * CC + c]) + b2[c];
        out[(size_t)d * CC + c] = r;
    }
}

// ---------------- launch ------------------------------------------------------
extern "C" void kernel_launch(void* const* d_in, const int* in_sizes, int n_in,
                              void* d_out, int out_size) {
    const float* x  = (const float*)d_in[0];
    const int*   ei = (const int*)d_in[1];
    const float* W1 = (const float*)d_in[2];
    const float* b1 = (const float*)d_in[3];
    const float* W2 = (const float*)d_in[4];
    const float* b2 = (const float*)d_in[5];

    int n = in_sizes[0] / FIN;   // 100000
    int e = in_sizes[1] / 2;     // 3200000
    const int* src = ei;
    const int* dst = ei + e;

    int nb = (n + 255) / 256;

    k_zero_deg<<<nb, 256>>>(n);
    k_hist<<<(e + 255) / 256, 256>>>(dst, e);
    k_bsum<<<nb, 256>>>(n);
    k_scan_bsum<<<1, 512>>>(nb);
    k_scan_final<<<nb, 256>>>(n, e);
    k_scatter<<<(e + 255) / 256, 256>>>(src, dst, e);
    k_gemm1<<<(n + BM - 1) / BM, 256>>>(x, W1, n);
    k_agg1<<<(n + 7) / 8, 256>>>(b1, W2, n);
    k_agg2<<<(n + 7) / 8, 256>>>(b2, (float*)d_out, n);
}

// round 3
// speedup vs baseline: 1.5237x; 1.5237x over previous
#include <cuda_runtime.h>
#include <cuda_bf16.h>
#include <cstdint>

#define NN   100000
#define EE   3200000
#define FIN  512
#define HH   64
#define CC   8

// ---------------- scratch (device globals; no runtime allocation) ----------
__device__ float g_h1[NN * HH];       // x @ W1
__device__ float g_t2[NN * CC];       // relu(agg1 + b1) @ W2
__device__ int   g_deg[NN];
__device__ float g_dinv[NN];
__device__ int   g_rowptr[NN + 1];
__device__ int   g_cursor[NN];
__device__ int   g_col[EE];
__device__ int   g_bsum[512];
__device__ int   g_boff[512];

// W1 pre-transposed to MMA-B layout: [chunk(8)][n(64)][PADK(72)] bf16, hi & lo
#define PADK 72
__device__ __nv_bfloat16 g_w1t_hi[8 * HH * PADK];
__device__ __nv_bfloat16 g_w1t_lo[8 * HH * PADK];

// ---------------- CSR construction ------------------------------------------
__global__ void k_zero_deg(int n) {
    int i = blockIdx.x * blockDim.x + threadIdx.x;
    if (i < n) g_deg[i] = 0;
}

__global__ void k_hist(const int* __restrict__ dst, int e) {
    int i = blockIdx.x * blockDim.x + threadIdx.x;
    if (i < e) atomicAdd(&g_deg[dst[i]], 1);
}

__global__ void k_bsum(int n) {
    __shared__ int s[256];
    int t = threadIdx.x;
    int i = blockIdx.x * 256 + t;
    s[t] = (i < n) ? g_deg[i] : 0;
    __syncthreads();
    for (int o = 128; o > 0; o >>= 1) {
        if (t < o) s[t] += s[t + o];
        __syncthreads();
    }
    if (t == 0) g_bsum[blockIdx.x] = s[0];
}

__global__ void k_scan_bsum(int nb) {
    __shared__ int s[512];
    int t = threadIdx.x;
    int v = (t < nb) ? g_bsum[t] : 0;
    s[t] = v;
    __syncthreads();
    for (int o = 1; o < 512; o <<= 1) {
        int a = (t >= o) ? s[t - o] : 0;
        __syncthreads();
        s[t] += a;
        __syncthreads();
    }
    if (t < nb) g_boff[t] = s[t] - v;
}

__global__ void k_scan_final(int n, int e) {
    __shared__ int s[256];
    int t = threadIdx.x;
    int i = blockIdx.x * 256 + t;
    int v = (i < n) ? g_deg[i] : 0;
    s[t] = v;
    __syncthreads();
    for (int o = 1; o < 256; o <<= 1) {
        int a = (t >= o) ? s[t - o] : 0;
        __syncthreads();
        s[t] += a;
        __syncthreads();
    }
    if (i < n) {
        int excl = g_boff[blockIdx.x] + s[t] - v;
        g_rowptr[i] = excl;
        g_cursor[i] = excl;
        g_dinv[i]   = rsqrtf((float)(v + 1));
    }
    if (i == 0) g_rowptr[n] = e;
}

__global__ void k_scatter(const int* __restrict__ src,
                          const int* __restrict__ dst, int e) {
    int i = blockIdx.x * blockDim.x + threadIdx.x;
    if (i < e) {
        int d   = dst[i];
        int pos = atomicAdd(&g_cursor[d], 1);
        g_col[pos] = src[i];
    }
}

// ---------------- W1 -> bf16 hi/lo transposed image -------------------------
__global__ void k_prep_w1(const float* __restrict__ W1) {
    int idx = blockIdx.x * 256 + threadIdx.x;      // n*512 + kg
    if (idx >= HH * FIN) return;
    int nn = idx >> 9;
    int kg = idx & 511;
    float v = W1[(size_t)kg * HH + nn];
    __nv_bfloat16 hi = __float2bfloat16(v);
    __nv_bfloat16 lo = __float2bfloat16(v - __bfloat162float(hi));
    int chunk = kg >> 6, k = kg & 63;
    int o = (chunk * HH + nn) * PADK + k;
    g_w1t_hi[o] = hi;
    g_w1t_lo[o] = lo;
}

// ---------------- GEMM1: h1 = x @ W1 via HMMA bf16 split --------------------
__device__ __forceinline__ void mma16816(float* c, uint32_t a0, uint32_t a1,
                                         uint32_t a2, uint32_t a3,
                                         uint32_t b0, uint32_t b1) {
    asm volatile(
        "mma.sync.aligned.m16n8k16.row.col.f32.bf16.bf16.f32 "
        "{%0,%1,%2,%3}, {%4,%5,%6,%7}, {%8,%9}, {%0,%1,%2,%3};"
        : "+f"(c[0]), "+f"(c[1]), "+f"(c[2]), "+f"(c[3])
        : "r"(a0), "r"(a1), "r"(a2), "r"(a3), "r"(b0), "r"(b1));
}

// smem: Ahi[128*72] Alo[128*72] Bhi[64*72] Blo[64*72] bf16
#define SM_AHI 0
#define SM_ALO (128 * PADK)
#define SM_BHI (256 * PADK)
#define SM_BLO (320 * PADK)
#define SMEM_GEMM ((384 * PADK) * 2)

__global__ __launch_bounds__(256) void k_gemm1_mma(const float* __restrict__ x,
                                                   int n) {
    extern __shared__ __nv_bfloat16 sm[];
    int tid = threadIdx.x, wid = tid >> 5, lane = tid & 31;
    int g = lane >> 2, t = lane & 3;
    int mBase = blockIdx.x * 128;

    float acc[8][4];
#pragma unroll
    for (int i = 0; i < 8; i++)
#pragma unroll
        for (int j = 0; j < 4; j++) acc[i][j] = 0.f;

    for (int chunk = 0; chunk < FIN / 64; chunk++) {
        int kb = chunk * 64;
        if (chunk) __syncthreads();

        // ---- A tile: 128 rows x 64 k from x (fp32), split hi/lo
#pragma unroll
        for (int l = 0; l < 8; l++) {
            int id  = tid + l * 256;     // 0..2047
            int row = id >> 4;
            int col = (id & 15) * 4;
            float4 v = make_float4(0.f, 0.f, 0.f, 0.f);
            int gr = mBase + row;
            if (gr < n) v = *(const float4*)&x[(size_t)gr * FIN + kb + col];
            __nv_bfloat16 h0 = __float2bfloat16(v.x);
            __nv_bfloat16 h1 = __float2bfloat16(v.y);
            __nv_bfloat16 h2 = __float2bfloat16(v.z);
            __nv_bfloat16 h3 = __float2bfloat16(v.w);
            uint32_t uh0 = ((uint32_t)__bfloat16_as_ushort(h1) << 16) |
                           __bfloat16_as_ushort(h0);
            uint32_t uh1 = ((uint32_t)__bfloat16_as_ushort(h3) << 16) |
                           __bfloat16_as_ushort(h2);
            __nv_bfloat16 l0 = __float2bfloat16(v.x - __bfloat162float(h0));
            __nv_bfloat16 l1 = __float2bfloat16(v.y - __bfloat162float(h1));
            __nv_bfloat16 l2 = __float2bfloat16(v.z - __bfloat162float(h2));
            __nv_bfloat16 l3 = __float2bfloat16(v.w - __bfloat162float(h3));
            uint32_t ul0 = ((uint32_t)__bfloat16_as_ushort(l1) << 16) |
                           __bfloat16_as_ushort(l0);
            uint32_t ul1 = ((uint32_t)__bfloat16_as_ushort(l3) << 16) |
                           __bfloat16_as_ushort(l2);
            int o = row * PADK + col;
            *(uint2*)&sm[SM_AHI + o] = make_uint2(uh0, uh1);
            *(uint2*)&sm[SM_ALO + o] = make_uint2(ul0, ul1);
        }

        // ---- B tile: contiguous copy of pre-transposed image (4608 bf16 each)
        {
            const uint4* shi = (const uint4*)&g_w1t_hi[chunk * HH * PADK];
            const uint4* slo = (const uint4*)&g_w1t_lo[chunk * HH * PADK];
            uint4* dhi = (uint4*)&sm[SM_BHI];
            uint4* dlo = (uint4*)&sm[SM_BLO];
            for (int i = tid; i < HH * PADK / 8; i += 256) {
                dhi[i] = shi[i];
                dlo[i] = slo[i];
            }
        }
        __syncthreads();

        // ---- MMAs: 4 k-steps x 8 n-tiles x 3 split terms
#pragma unroll
        for (int ks = 0; ks < 4; ks++) {
            int k0 = ks * 16;
            const __nv_bfloat16* ah = &sm[SM_AHI + (wid * 16 + g) * PADK + k0 + t * 2];
            const __nv_bfloat16* al = &sm[SM_ALO + (wid * 16 + g) * PADK + k0 + t * 2];
            uint32_t ah0 = *(const uint32_t*)ah;
            uint32_t ah1 = *(const uint32_t*)(ah + 8 * PADK);
            uint32_t ah2 = *(const uint32_t*)(ah + 8);
            uint32_t ah3 = *(const uint32_t*)(ah + 8 * PADK + 8);
            uint32_t al0 = *(const uint32_t*)al;
            uint32_t al1 = *(const uint32_t*)(al + 8 * PADK);
            uint32_t al2 = *(const uint32_t*)(al + 8);
            uint32_t al3 = *(const uint32_t*)(al + 8 * PADK + 8);
#pragma unroll
            for (int nt = 0; nt < 8; nt++) {
                const __nv_bfloat16* bh = &sm[SM_BHI + (nt * 8 + g) * PADK + k0 + t * 2];
                const __nv_bfloat16* bl = &sm[SM_BLO + (nt * 8 + g) * PADK + k0 + t * 2];
                uint32_t bh0 = *(const uint32_t*)bh;
                uint32_t bh1 = *(const uint32_t*)(bh + 8);
                uint32_t bl0 = *(const uint32_t*)bl;
                uint32_t bl1 = *(const uint32_t*)(bl + 8);
                mma16816(acc[nt], ah0, ah1, ah2, ah3, bh0, bh1);
                mma16816(acc[nt], ah0, ah1, ah2, ah3, bl0, bl1);
                mma16816(acc[nt], al0, al1, al2, al3, bh0, bh1);
            }
        }
    }

    // ---- epilogue: fragment rows g / g+8, cols nt*8 + t*2
    int r0 = mBase + wid * 16 + g;
#pragma unroll
    for (int nt = 0; nt < 8; nt++) {
        int col = nt * 8 + t * 2;
        if (r0 < n)
            *(float2*)&g_h1[(size_t)r0 * HH + col] = make_float2(acc[nt][0], acc[nt][1]);
        if (r0 + 8 < n)
            *(float2*)&g_h1[(size_t)(r0 + 8) * HH + col] = make_float2(acc[nt][2], acc[nt][3]);
    }
}

// ---------------- layer-1 aggregate + bias + ReLU + @W2 ---------------------
__global__ __launch_bounds__(256) void k_agg1(const float* __restrict__ b1,
                                              const float* __restrict__ W2,
                                              int n) {
    __shared__ float b1s[HH];
    __shared__ float w2t[CC * HH];

    int tid = threadIdx.x;
    if (tid < HH) b1s[tid] = b1[tid];
    for (int i = tid; i < CC * HH; i += 256) {
        int c = i >> 6, k = i & 63;
        w2t[i] = W2[k * CC + c];
    }
    __syncthreads();

    int warp = tid >> 5, lane = tid & 31;
    int d = blockIdx.x * 8 + warp;
    if (d >= n) return;

    float dd = g_dinv[d];
    const float2* h2 = (const float2*)g_h1;

    float2 self = h2[(size_t)d * 32 + lane];
    float2 acc;
    acc.x = self.x * dd * dd;
    acc.y = self.y * dd * dd;

    int e   = g_rowptr[d];
    int end = g_rowptr[d + 1];
    for (; e + 4 <= end; e += 4) {
        int s0 = g_col[e], s1 = g_col[e + 1], s2 = g_col[e + 2], s3 = g_col[e + 3];
        float w0 = g_dinv[s0] * dd;
        float w1 = g_dinv[s1] * dd;
        float w2 = g_dinv[s2] * dd;
        float w3 = g_dinv[s3] * dd;
        float2 v0 = h2[(size_t)s0 * 32 + lane];
        float2 v1 = h2[(size_t)s1 * 32 + lane];
        float2 v2 = h2[(size_t)s2 * 32 + lane];
        float2 v3 = h2[(size_t)s3 * 32 + lane];
        acc.x += w0 * v0.x + w1 * v1.x + w2 * v2.x + w3 * v3.x;
        acc.y += w0 * v0.y + w1 * v1.y + w2 * v2.y + w3 * v3.y;
    }
    for (; e < end; e++) {
        int s = g_col[e];
        float w = g_dinv[s] * dd;
        float2 v = h2[(size_t)s * 32 + lane];
        acc.x += w * v.x;
        acc.y += w * v.y;
    }

    float hx = fmaxf(acc.x + b1s[2 * lane], 0.f);
    float hy = fmaxf(acc.y + b1s[2 * lane + 1], 0.f);

    float pw[8];
#pragma unroll
    for (int c = 0; c < 8; c++) {
        float2 q = *(float2*)&w2t[c * HH + 2 * lane];
        pw[c] = hx * q.x + hy * q.y;
    }
#pragma unroll
    for (int c = 0; c < 8; c++) {
        pw[c] += __shfl_down_sync(0xffffffffu, pw[c], 16);
        pw[c] += __shfl_down_sync(0xffffffffu, pw[c], 8);
        pw[c] += __shfl_down_sync(0xffffffffu, pw[c], 4);
        pw[c] += __shfl_down_sync(0xffffffffu, pw[c], 2);
        pw[c] += __shfl_down_sync(0xffffffffu, pw[c], 1);
    }
    if (lane == 0) {
        *(float4*)&g_t2[(size_t)d * CC]     = make_float4(pw[0], pw[1], pw[2], pw[3]);
        *(float4*)&g_t2[(size_t)d * CC + 4] = make_float4(pw[4], pw[5], pw[6], pw[7]);
    }
}

// ---------------- layer-2 aggregate + b2 -> out ------------------------------
__global__ __launch_bounds__(256) void k_agg2(const float* __restrict__ b2,
                                              float* __restrict__ out, int n) {
    int tid  = threadIdx.x;
    int warp = tid >> 5, lane = tid & 31;
    int d = blockIdx.x * 8 + warp;
    if (d >= n) return;
    int j = lane >> 3, c = lane & 7;

    float dd  = g_dinv[d];
    int beg   = g_rowptr[d];
    int end   = g_rowptr[d + 1];
    float acc = 0.f;
    for (int e = beg + j; e < end; e += 4) {
        int s = g_col[e];
        acc += g_dinv[s] * g_t2[(size_t)s * CC + c];
    }
    acc += __shfl_down_sync(0xffffffffu, acc, 16);
    acc += __shfl_down_sync(0xffffffffu, acc, 8);
    if (j == 0) {
        float r = dd * (acc + dd * g_t2[(size_t)d * CC + c]) + b2[c];
        out[(size_t)d * CC + c] = r;
    }
}

// ---------------- launch ------------------------------------------------------
extern "C" void kernel_launch(void* const* d_in, const int* in_sizes, int n_in,
                              void* d_out, int out_size) {
    const float* x  = (const float*)d_in[0];
    const int*   ei = (const int*)d_in[1];
    const float* W1 = (const float*)d_in[2];
    const float* b1 = (const float*)d_in[3];
    const float* W2 = (const float*)d_in[4];
    const float* b2 = (const float*)d_in[5];

    int n = in_sizes[0] / FIN;   // 100000
    int e = in_sizes[1] / 2;     // 3200000
    const int* src = ei;
    const int* dst = ei + e;

    int nb = (n + 255) / 256;

    cudaFuncSetAttribute(k_gemm1_mma, cudaFuncAttributeMaxDynamicSharedMemorySize,
                         SMEM_GEMM);

    k_zero_deg<<<nb, 256>>>(n);
    k_hist<<<(e + 255) / 256, 256>>>(dst, e);
    k_bsum<<<nb, 256>>>(n);
    k_scan_bsum<<<1, 512>>>(nb);
    k_scan_final<<<nb, 256>>>(n, e);
    k_scatter<<<(e + 255) / 256, 256>>>(src, dst, e);
    k_prep_w1<<<(HH * FIN + 255) / 256, 256>>>(W1);
    k_gemm1_mma<<<(n + 127) / 128, 256, SMEM_GEMM>>>(x, n);
    k_agg1<<<(n + 7) / 8, 256>>>(b1, W2, n);
    k_agg2<<<(n + 7) / 8, 256>>>(b2, (float*)d_out, n);
}

// round 4
// speedup vs baseline: 1.7382x; 1.1408x over previous
#include <cuda_runtime.h>
#include <cuda_fp16.h>
#include <cuda_bf16.h>
#include <cstdint>

#define NN   100000
#define EE   3200000
#define FIN  512
#define HH   64
#define CC   8

// ---------------- scratch (device globals; no runtime allocation) ----------
__device__ __half g_h1h[NN * HH];     // fp16(x @ W1)
__device__ float g_t2[NN * CC];       // dinv[d] * (relu(agg1 + b1) @ W2)
__device__ int   g_deg[NN];
__device__ float g_dinv[NN];
__device__ int   g_rowptr[NN + 1];
__device__ int   g_cursor[NN];
__device__ int   g_col[EE];
__device__ int   g_bsum[512];
__device__ int   g_boff[512];

// W1 pre-transposed to MMA-B layout: [chunk(8)][n(64)][PADK(72)] bf16, hi & lo
#define PADK 72
__device__ __nv_bfloat16 g_w1t_hi[8 * HH * PADK];
__device__ __nv_bfloat16 g_w1t_lo[8 * HH * PADK];

// ---------------- stream fork/join infra (host, created at load) ------------
static cudaStream_t g_s2 = nullptr;
static cudaEvent_t  g_evA = nullptr, g_evB = nullptr;
namespace {
struct StreamInit {
    StreamInit() {
        if (cudaStreamCreateWithFlags(&g_s2, cudaStreamNonBlocking) != cudaSuccess)
            g_s2 = nullptr;
        if (g_s2) {
            if (cudaEventCreateWithFlags(&g_evA, cudaEventDisableTiming) != cudaSuccess ||
                cudaEventCreateWithFlags(&g_evB, cudaEventDisableTiming) != cudaSuccess) {
                g_s2 = nullptr;
            }
        }
    }
};
StreamInit g_stream_init;
}

// ---------------- CSR construction ------------------------------------------
__global__ void k_hist(const int* __restrict__ dst, int e) {
    int i = blockIdx.x * blockDim.x + threadIdx.x;
    if (i < e) atomicAdd(&g_deg[dst[i]], 1);
}

__global__ void k_bsum(int n) {
    __shared__ int s[256];
    int t = threadIdx.x;
    int i = blockIdx.x * 256 + t;
    s[t] = (i < n) ? g_deg[i] : 0;
    __syncthreads();
    for (int o = 128; o > 0; o >>= 1) {
        if (t < o) s[t] += s[t + o];
        __syncthreads();
    }
    if (t == 0) g_bsum[blockIdx.x] = s[0];
}

__global__ void k_scan_bsum(int nb) {
    __shared__ int s[512];
    int t = threadIdx.x;
    int v = (t < nb) ? g_bsum[t] : 0;
    s[t] = v;
    __syncthreads();
    for (int o = 1; o < 512; o <<= 1) {
        int a = (t >= o) ? s[t - o] : 0;
        __syncthreads();
        s[t] += a;
        __syncthreads();
    }
    if (t < nb) g_boff[t] = s[t] - v;
}

__global__ void k_scan_final(int n, int e) {
    __shared__ int s[256];
    int t = threadIdx.x;
    int i = blockIdx.x * 256 + t;
    int v = (i < n) ? g_deg[i] : 0;
    s[t] = v;
    __syncthreads();
    for (int o = 1; o < 256; o <<= 1) {
        int a = (t >= o) ? s[t - o] : 0;
        __syncthreads();
        s[t] += a;
        __syncthreads();
    }
    if (i < n) {
        int excl = g_boff[blockIdx.x] + s[t] - v;
        g_rowptr[i] = excl;
        g_cursor[i] = excl;
        g_dinv[i]   = rsqrtf((float)(v + 1));
    }
    if (i == 0) g_rowptr[n] = e;
}

__global__ void k_scatter(const int* __restrict__ src,
                          const int* __restrict__ dst, int e) {
    int i = blockIdx.x * blockDim.x + threadIdx.x;
    if (i < e) {
        int d   = dst[i];
        int pos = atomicAdd(&g_cursor[d], 1);
        g_col[pos] = src[i];
    }
}

// ---------------- W1 -> bf16 hi/lo transposed image -------------------------
__global__ void k_prep_w1(const float* __restrict__ W1) {
    int idx = blockIdx.x * 256 + threadIdx.x;      // n*512 + kg
    if (idx >= HH * FIN) return;
    int nn = idx >> 9;
    int kg = idx & 511;
    float v = W1[(size_t)kg * HH + nn];
    __nv_bfloat16 hi = __float2bfloat16(v);
    __nv_bfloat16 lo = __float2bfloat16(v - __bfloat162float(hi));
    int chunk = kg >> 6, k = kg & 63;
    int o = (chunk * HH + nn) * PADK + k;
    g_w1t_hi[o] = hi;
    g_w1t_lo[o] = lo;
}

// ---------------- GEMM1: h1 = fp16(x @ W1) via HMMA bf16 split --------------
__device__ __forceinline__ void mma16816(float* c, uint32_t a0, uint32_t a1,
                                         uint32_t a2, uint32_t a3,
                                         uint32_t b0, uint32_t b1) {
    asm volatile(
        "mma.sync.aligned.m16n8k16.row.col.f32.bf16.bf16.f32 "
        "{%0,%1,%2,%3}, {%4,%5,%6,%7}, {%8,%9}, {%0,%1,%2,%3};"
        : "+f"(c[0]), "+f"(c[1]), "+f"(c[2]), "+f"(c[3])
        : "r"(a0), "r"(a1), "r"(a2), "r"(a3), "r"(b0), "r"(b1));
}

#define SM_AHI 0
#define SM_ALO (128 * PADK)
#define SM_BHI (256 * PADK)
#define SM_BLO (320 * PADK)
#define SMEM_GEMM ((384 * PADK) * 2)

__global__ __launch_bounds__(256) void k_gemm1_mma(const float* __restrict__ x,
                                                   int n) {
    extern __shared__ __nv_bfloat16 sm[];
    int tid = threadIdx.x, wid = tid >> 5, lane = tid & 31;
    int g = lane >> 2, t = lane & 3;
    int mBase = blockIdx.x * 128;

    float acc[8][4];
#pragma unroll
    for (int i = 0; i < 8; i++)
#pragma unroll
        for (int j = 0; j < 4; j++) acc[i][j] = 0.f;

    for (int chunk = 0; chunk < FIN / 64; chunk++) {
        int kb = chunk * 64;
        if (chunk) __syncthreads();

        // ---- A tile: 128 rows x 64 k from x (fp32), split hi/lo
#pragma unroll
        for (int l = 0; l < 8; l++) {
            int id  = tid + l * 256;
            int row = id >> 4;
            int col = (id & 15) * 4;
            float4 v = make_float4(0.f, 0.f, 0.f, 0.f);
            int gr = mBase + row;
            if (gr < n) v = *(const float4*)&x[(size_t)gr * FIN + kb + col];
            __nv_bfloat16 h0 = __float2bfloat16(v.x);
            __nv_bfloat16 h1 = __float2bfloat16(v.y);
            __nv_bfloat16 h2 = __float2bfloat16(v.z);
            __nv_bfloat16 h3 = __float2bfloat16(v.w);
            uint32_t uh0 = ((uint32_t)__bfloat16_as_ushort(h1) << 16) |
                           __bfloat16_as_ushort(h0);
            uint32_t uh1 = ((uint32_t)__bfloat16_as_ushort(h3) << 16) |
                           __bfloat16_as_ushort(h2);
            __nv_bfloat16 l0 = __float2bfloat16(v.x - __bfloat162float(h0));
            __nv_bfloat16 l1 = __float2bfloat16(v.y - __bfloat162float(h1));
            __nv_bfloat16 l2 = __float2bfloat16(v.z - __bfloat162float(h2));
            __nv_bfloat16 l3 = __float2bfloat16(v.w - __bfloat162float(h3));
            uint32_t ul0 = ((uint32_t)__bfloat16_as_ushort(l1) << 16) |
                           __bfloat16_as_ushort(l0);
            uint32_t ul1 = ((uint32_t)__bfloat16_as_ushort(l3) << 16) |
                           __bfloat16_as_ushort(l2);
            int o = row * PADK + col;
            *(uint2*)&sm[SM_AHI + o] = make_uint2(uh0, uh1);
            *(uint2*)&sm[SM_ALO + o] = make_uint2(ul0, ul1);
        }

        // ---- B tile: contiguous copy of pre-transposed image
        {
            const uint4* shi = (const uint4*)&g_w1t_hi[chunk * HH * PADK];
            const uint4* slo = (const uint4*)&g_w1t_lo[chunk * HH * PADK];
            uint4* dhi = (uint4*)&sm[SM_BHI];
            uint4* dlo = (uint4*)&sm[SM_BLO];
            for (int i = tid; i < HH * PADK / 8; i += 256) {
                dhi[i] = shi[i];
                dlo[i] = slo[i];
            }
        }
        __syncthreads();

#pragma unroll
        for (int ks = 0; ks < 4; ks++) {
            int k0 = ks * 16;
            const __nv_bfloat16* ah = &sm[SM_AHI + (wid * 16 + g) * PADK + k0 + t * 2];
            const __nv_bfloat16* al = &sm[SM_ALO + (wid * 16 + g) * PADK + k0 + t * 2];
            uint32_t ah0 = *(const uint32_t*)ah;
            uint32_t ah1 = *(const uint32_t*)(ah + 8 * PADK);
            uint32_t ah2 = *(const uint32_t*)(ah + 8);
            uint32_t ah3 = *(const uint32_t*)(ah + 8 * PADK + 8);
            uint32_t al0 = *(const uint32_t*)al;
            uint32_t al1 = *(const uint32_t*)(al + 8 * PADK);
            uint32_t al2 = *(const uint32_t*)(al + 8);
            uint32_t al3 = *(const uint32_t*)(al + 8 * PADK + 8);
#pragma unroll
            for (int nt = 0; nt < 8; nt++) {
                const __nv_bfloat16* bh = &sm[SM_BHI + (nt * 8 + g) * PADK + k0 + t * 2];
                const __nv_bfloat16* bl = &sm[SM_BLO + (nt * 8 + g) * PADK + k0 + t * 2];
                uint32_t bh0 = *(const uint32_t*)bh;
                uint32_t bh1 = *(const uint32_t*)(bh + 8);
                uint32_t bl0 = *(const uint32_t*)bl;
                uint32_t bl1 = *(const uint32_t*)(bl + 8);
                mma16816(acc[nt], ah0, ah1, ah2, ah3, bh0, bh1);
                mma16816(acc[nt], ah0, ah1, ah2, ah3, bl0, bl1);
                mma16816(acc[nt], al0, al1, al2, al3, bh0, bh1);
            }
        }
    }

    // ---- epilogue: emit fp16 h1
    int r0 = mBase + wid * 16 + g;
#pragma unroll
    for (int nt = 0; nt < 8; nt++) {
        int col = nt * 8 + t * 2;
        if (r0 < n)
            *(__half2*)&g_h1h[(size_t)r0 * HH + col] =
                __floats2half2_rn(acc[nt][0], acc[nt][1]);
        if (r0 + 8 < n)
            *(__half2*)&g_h1h[(size_t)(r0 + 8) * HH + col] =
                __floats2half2_rn(acc[nt][2], acc[nt][3]);
    }
}

// ---------------- layer-1 aggregate + bias + ReLU + @W2 ---------------------
// warp per dst; lane owns half2 slot 'lane' (features 2*lane, 2*lane+1)
__global__ __launch_bounds__(256) void k_agg1(const float* __restrict__ b1,
                                              const float* __restrict__ W2,
                                              int n) {
    __shared__ float b1s[HH];
    __shared__ float w2t[CC * HH];

    int tid = threadIdx.x;
    if (tid < HH) b1s[tid] = b1[tid];
    for (int i = tid; i < CC * HH; i += 256) {
        int c = i >> 6, k = i & 63;
        w2t[i] = W2[k * CC + c];
    }
    __syncthreads();

    int warp = tid >> 5, lane = tid & 31;
    int d = blockIdx.x * 8 + warp;
    if (d >= n) return;

    float dd = g_dinv[d];
    const __half2* h2 = (const __half2*)g_h1h;

    float2 self = __half22float2(h2[(size_t)d * 32 + lane]);
    float2 acc;                            // = sum of dinv[s]*h[s] (+ dd*h[d])
    acc.x = self.x * dd;
    acc.y = self.y * dd;

    int e   = g_rowptr[d];
    int end = g_rowptr[d + 1];
    for (; e + 4 <= end; e += 4) {
        int s0 = g_col[e], s1 = g_col[e + 1], s2 = g_col[e + 2], s3 = g_col[e + 3];
        float w0 = g_dinv[s0];
        float w1 = g_dinv[s1];
        float w2 = g_dinv[s2];
        float w3 = g_dinv[s3];
        float2 v0 = __half22float2(h2[(size_t)s0 * 32 + lane]);
        float2 v1 = __half22float2(h2[(size_t)s1 * 32 + lane]);
        float2 v2 = __half22float2(h2[(size_t)s2 * 32 + lane]);
        float2 v3 = __half22float2(h2[(size_t)s3 * 32 + lane]);
        acc.x += w0 * v0.x + w1 * v1.x + w2 * v2.x + w3 * v3.x;
        acc.y += w0 * v0.y + w1 * v1.y + w2 * v2.y + w3 * v3.y;
    }
    for (; e < end; e++) {
        int s = g_col[e];
        float w = g_dinv[s];
        float2 v = __half22float2(h2[(size_t)s * 32 + lane]);
        acc.x += w * v.x;
        acc.y += w * v.y;
    }

    float hx = fmaxf(dd * acc.x + b1s[2 * lane], 0.f);
    float hy = fmaxf(dd * acc.y + b1s[2 * lane + 1], 0.f);

    float pw[8];
#pragma unroll
    for (int c = 0; c < 8; c++) {
        float2 q = *(float2*)&w2t[c * HH + 2 * lane];
        pw[c] = hx * q.x + hy * q.y;
    }
#pragma unroll
    for (int c = 0; c < 8; c++) {
        pw[c] += __shfl_down_sync(0xffffffffu, pw[c], 16);
        pw[c] += __shfl_down_sync(0xffffffffu, pw[c], 8);
        pw[c] += __shfl_down_sync(0xffffffffu, pw[c], 4);
        pw[c] += __shfl_down_sync(0xffffffffu, pw[c], 2);
        pw[c] += __shfl_down_sync(0xffffffffu, pw[c], 1);
    }
    if (lane == 0) {
        // store t2' = dinv[d] * (relu(h) @ W2)   (pre-scaled for layer 2)
        *(float4*)&g_t2[(size_t)d * CC] =
            make_float4(dd * pw[0], dd * pw[1], dd * pw[2], dd * pw[3]);
        *(float4*)&g_t2[(size_t)d * CC + 4] =
            make_float4(dd * pw[4], dd * pw[5], dd * pw[6], dd * pw[7]);
    }
}

// ---------------- layer-2 aggregate + b2 -> out ------------------------------
// out[d] = dd * (sum_edges t2'[s] + t2'[d]) + b2
__global__ __launch_bounds__(256) void k_agg2(const float* __restrict__ b2,
                                              float* __restrict__ out, int n) {
    int tid  = threadIdx.x;
    int warp = tid >> 5, lane = tid & 31;
    int d = blockIdx.x * 8 + warp;
    if (d >= n) return;
    int j = lane >> 3, c = lane & 7;

    float dd  = g_dinv[d];
    int beg   = g_rowptr[d];
    int end   = g_rowptr[d + 1];
    float acc = 0.f;
    for (int e = beg + j; e < end; e += 4) {
        int s = g_col[e];
        acc += g_t2[(size_t)s * CC + c];
    }
    acc += __shfl_down_sync(0xffffffffu, acc, 16);
    acc += __shfl_down_sync(0xffffffffu, acc, 8);
    if (j == 0) {
        float r = dd * (acc + g_t2[(size_t)d * CC + c]) + b2[c];
        out[(size_t)d * CC + c] = r;
    }
}

// ---------------- launch ------------------------------------------------------
extern "C" void kernel_launch(void* const* d_in, const int* in_sizes, int n_in,
                              void* d_out, int out_size) {
    const float* x  = (const float*)d_in[0];
    const int*   ei = (const int*)d_in[1];
    const float* W1 = (const float*)d_in[2];
    const float* b1 = (const float*)d_in[3];
    const float* W2 = (const float*)d_in[4];
    const float* b2 = (const float*)d_in[5];

    int n = in_sizes[0] / FIN;   // 100000
    int e = in_sizes[1] / 2;     // 3200000
    const int* src = ei;
    const int* dst = ei + e;

    int nb = (n + 255) / 256;

    cudaFuncSetAttribute(k_gemm1_mma, cudaFuncAttributeMaxDynamicSharedMemorySize,
                         SMEM_GEMM);

    void* degAddr = nullptr;
    cudaGetSymbolAddress(&degAddr, g_deg);

    if (g_s2) {
        // fork: GEMM path on g_s2, CSR path on main stream
        cudaEventRecord(g_evA, 0);
        cudaStreamWaitEvent(g_s2, g_evA, 0);
        k_prep_w1<<<(HH * FIN + 255) / 256, 256, 0, g_s2>>>(W1);
        k_gemm1_mma<<<(n + 127) / 128, 256, SMEM_GEMM, g_s2>>>(x, n);
        cudaEventRecord(g_evB, g_s2);

        cudaMemsetAsync(degAddr, 0, (size_t)n * sizeof(int), 0);
        k_hist<<<(e + 255) / 256, 256>>>(dst, e);
        k_bsum<<<nb, 256>>>(n);
        k_scan_bsum<<<1, 512>>>(nb);
        k_scan_final<<<nb, 256>>>(n, e);
        k_scatter<<<(e + 255) / 256, 256>>>(src, dst, e);

        cudaStreamWaitEvent(0, g_evB, 0);   // join
    } else {
        cudaMemsetAsync(degAddr, 0, (size_t)n * sizeof(int), 0);
        k_hist<<<(e + 255) / 256, 256>>>(dst, e);
        k_bsum<<<nb, 256>>>(n);
        k_scan_bsum<<<1, 512>>>(nb);
        k_scan_final<<<nb, 256>>>(n, e);
        k_scatter<<<(e + 255) / 256, 256>>>(src, dst, e);
        k_prep_w1<<<(HH * FIN + 255) / 256, 256>>>(W1);
        k_gemm1_mma<<<(n + 127) / 128, 256, SMEM_GEMM>>>(x, n);
    }

    k_agg1<<<(n + 7) / 8, 256>>>(b1, W2, n);
    k_agg2<<<(n + 7) / 8, 256>>>(b2, (float*)d_out, n);
}

// round 6
// speedup vs baseline: 1.8954x; 1.0904x over previous
#include <cuda_runtime.h>
#include <cuda_fp16.h>
#include <cuda_bf16.h>
#include <cstdint>

#define NN   100000
#define EE   3200000
#define FIN  512
#define HH   64
#define CC   8

// ---------------- scratch (device globals; no runtime allocation) ----------
__device__ __half g_h1h[NN * HH];     // fp16(x @ W1)
__device__ float g_t2[NN * CC];       // dinv[d] * (relu(agg1 + b1) @ W2)
__device__ int   g_deg[NN];
__device__ float g_dinv[NN];
__device__ int   g_rowptr[NN + 1];
__device__ int   g_cursor[NN];
__device__ int   g_col[EE];
__device__ int   g_bsum[512];
__device__ int   g_boff[512];

// W1 pre-transposed to MMA-B layout: [chunk(8)][n(64)][PADK(72)] bf16, hi & lo
#define PADK 72
__device__ __nv_bfloat16 g_w1t_hi[8 * HH * PADK];
__device__ __nv_bfloat16 g_w1t_lo[8 * HH * PADK];

// ---------------- stream fork/join infra (host, created at load) ------------
static cudaStream_t g_s2 = nullptr;
static cudaEvent_t  g_evA = nullptr, g_evB = nullptr;
namespace {
struct StreamInit {
    StreamInit() {
        if (cudaStreamCreateWithFlags(&g_s2, cudaStreamNonBlocking) != cudaSuccess)
            g_s2 = nullptr;
        if (g_s2) {
            if (cudaEventCreateWithFlags(&g_evA, cudaEventDisableTiming) != cudaSuccess ||
                cudaEventCreateWithFlags(&g_evB, cudaEventDisableTiming) != cudaSuccess) {
                g_s2 = nullptr;
            }
        }
    }
};
StreamInit g_stream_init;
}

// ---------------- CSR construction ------------------------------------------
__global__ void k_hist(const int* __restrict__ dst, int e) {
    int i = blockIdx.x * blockDim.x + threadIdx.x;
    if (i < e) atomicAdd(&g_deg[dst[i]], 1);
}

__global__ void k_bsum(int n) {
    __shared__ int s[256];
    int t = threadIdx.x;
    int i = blockIdx.x * 256 + t;
    s[t] = (i < n) ? g_deg[i] : 0;
    __syncthreads();
    for (int o = 128; o > 0; o >>= 1) {
        if (t < o) s[t] += s[t + o];
        __syncthreads();
    }
    if (t == 0) g_bsum[blockIdx.x] = s[0];
}

__global__ void k_scan_bsum(int nb) {
    __shared__ int s[512];
    int t = threadIdx.x;
    int v = (t < nb) ? g_bsum[t] : 0;
    s[t] = v;
    __syncthreads();
    for (int o = 1; o < 512; o <<= 1) {
        int a = (t >= o) ? s[t - o] : 0;
        __syncthreads();
        s[t] += a;
        __syncthreads();
    }
    if (t < nb) g_boff[t] = s[t] - v;
}

__global__ void k_scan_final(int n, int e) {
    __shared__ int s[256];
    int t = threadIdx.x;
    int i = blockIdx.x * 256 + t;
    int v = (i < n) ? g_deg[i] : 0;
    s[t] = v;
    __syncthreads();
    for (int o = 1; o < 256; o <<= 1) {
        int a = (t >= o) ? s[t - o] : 0;
        __syncthreads();
        s[t] += a;
        __syncthreads();
    }
    if (i < n) {
        int excl = g_boff[blockIdx.x] + s[t] - v;
        g_rowptr[i] = excl;
        g_cursor[i] = excl;
        g_dinv[i]   = rsqrtf((float)(v + 1));
    }
    if (i == 0) g_rowptr[n] = e;
}

__global__ void k_scatter(const int* __restrict__ src,
                          const int* __restrict__ dst, int e) {
    int i = blockIdx.x * blockDim.x + threadIdx.x;
    if (i < e) {
        int d   = dst[i];
        int pos = atomicAdd(&g_cursor[d], 1);
        g_col[pos] = src[i];
    }
}

// ---------------- W1 -> bf16 hi/lo transposed image -------------------------
__global__ void k_prep_w1(const float* __restrict__ W1) {
    int idx = blockIdx.x * 256 + threadIdx.x;      // n*512 + kg
    if (idx >= HH * FIN) return;
    int nn = idx >> 9;
    int kg = idx & 511;
    float v = W1[(size_t)kg * HH + nn];
    __nv_bfloat16 hi = __float2bfloat16(v);
    __nv_bfloat16 lo = __float2bfloat16(v - __bfloat162float(hi));
    int chunk = kg >> 6, k = kg & 63;
    int o = (chunk * HH + nn) * PADK + k;
    g_w1t_hi[o] = hi;
    g_w1t_lo[o] = lo;
}

// ---------------- GEMM1: h1 = fp16(x @ W1) via HMMA bf16 split --------------
__device__ __forceinline__ void mma16816(float* c, uint32_t a0, uint32_t a1,
                                         uint32_t a2, uint32_t a3,
                                         uint32_t b0, uint32_t b1) {
    asm volatile(
        "mma.sync.aligned.m16n8k16.row.col.f32.bf16.bf16.f32 "
        "{%0,%1,%2,%3}, {%4,%5,%6,%7}, {%8,%9}, {%0,%1,%2,%3};"
        : "+f"(c[0]), "+f"(c[1]), "+f"(c[2]), "+f"(c[3])
        : "r"(a0), "r"(a1), "r"(a2), "r"(a3), "r"(b0), "r"(b1));
}

// cvt.rn.bf16x2.f32 d, a, b  ->  d.hi = bf16(a), d.lo = bf16(b)
__device__ __forceinline__ uint32_t bf16x2_rn(float up, float lo) {
    uint32_t r;
    asm("cvt.rn.bf16x2.f32 %0, %1, %2;" : "=r"(r) : "f"(up), "f"(lo));
    return r;
}

#define SM_AHI 0
#define SM_ALO (128 * PADK)
#define SM_BHI (256 * PADK)
#define SM_BLO (320 * PADK)
#define SMEM_GEMM ((384 * PADK) * 2)

__global__ __launch_bounds__(256) void k_gemm1_mma(const float* __restrict__ x,
                                                   int n) {
    extern __shared__ __nv_bfloat16 sm[];
    int tid = threadIdx.x, wid = tid >> 5, lane = tid & 31;
    int g = lane >> 2, t = lane & 3;
    int mBase = blockIdx.x * 128;

    float acc[8][4];
#pragma unroll
    for (int i = 0; i < 8; i++)
#pragma unroll
        for (int j = 0; j < 4; j++) acc[i][j] = 0.f;

    for (int chunk = 0; chunk < FIN / 64; chunk++) {
        int kb = chunk * 64;
        if (chunk) __syncthreads();

        // ---- A tile: 128 rows x 64 k from x (fp32), split hi/lo (bf16x2 cvt)
#pragma unroll
        for (int l = 0; l < 8; l++) {
            int id  = tid + l * 256;
            int row = id >> 4;
            int col = (id & 15) * 4;
            float4 v = make_float4(0.f, 0.f, 0.f, 0.f);
            int gr = mBase + row;
            if (gr < n) v = *(const float4*)&x[(size_t)gr * FIN + kb + col];
            uint32_t uh0 = bf16x2_rn(v.y, v.x);       // {bf(v.y)|bf(v.x)}
            uint32_t uh1 = bf16x2_rn(v.w, v.z);
            float h0f = __uint_as_float(uh0 << 16);
            float h1f = __uint_as_float(uh0 & 0xFFFF0000u);
            float h2f = __uint_as_float(uh1 << 16);
            float h3f = __uint_as_float(uh1 & 0xFFFF0000u);
            uint32_t ul0 = bf16x2_rn(v.y - h1f, v.x - h0f);
            uint32_t ul1 = bf16x2_rn(v.w - h3f, v.z - h2f);
            int o = row * PADK + col;
            *(uint2*)&sm[SM_AHI + o] = make_uint2(uh0, uh1);
            *(uint2*)&sm[SM_ALO + o] = make_uint2(ul0, ul1);
        }

        // ---- B tile: contiguous copy of pre-transposed image
        {
            const uint4* shi = (const uint4*)&g_w1t_hi[chunk * HH * PADK];
            const uint4* slo = (const uint4*)&g_w1t_lo[chunk * HH * PADK];
            uint4* dhi = (uint4*)&sm[SM_BHI];
            uint4* dlo = (uint4*)&sm[SM_BLO];
            for (int i = tid; i < HH * PADK / 8; i += 256) {
                dhi[i] = shi[i];
                dlo[i] = slo[i];
            }
        }
        __syncthreads();

#pragma unroll
        for (int ks = 0; ks < 4; ks++) {
            int k0 = ks * 16;
            const __nv_bfloat16* ah = &sm[SM_AHI + (wid * 16 + g) * PADK + k0 + t * 2];
            const __nv_bfloat16* al = &sm[SM_ALO + (wid * 16 + g) * PADK + k0 + t * 2];
            uint32_t ah0 = *(const uint32_t*)ah;
            uint32_t ah1 = *(const uint32_t*)(ah + 8 * PADK);
            uint32_t ah2 = *(const uint32_t*)(ah + 8);
            uint32_t ah3 = *(const uint32_t*)(ah + 8 * PADK + 8);
            uint32_t al0 = *(const uint32_t*)al;
            uint32_t al1 = *(const uint32_t*)(al + 8 * PADK);
            uint32_t al2 = *(const uint32_t*)(al + 8);
            uint32_t al3 = *(const uint32_t*)(al + 8 * PADK + 8);
#pragma unroll
            for (int nt = 0; nt < 8; nt++) {
                const __nv_bfloat16* bh = &sm[SM_BHI + (nt * 8 + g) * PADK + k0 + t * 2];
                const __nv_bfloat16* bl = &sm[SM_BLO + (nt * 8 + g) * PADK + k0 + t * 2];
                uint32_t bh0 = *(const uint32_t*)bh;
                uint32_t bh1 = *(const uint32_t*)(bh + 8);
                uint32_t bl0 = *(const uint32_t*)bl;
                uint32_t bl1 = *(const uint32_t*)(bl + 8);
                mma16816(acc[nt], ah0, ah1, ah2, ah3, bh0, bh1);
                mma16816(acc[nt], ah0, ah1, ah2, ah3, bl0, bl1);
                mma16816(acc[nt], al0, al1, al2, al3, bh0, bh1);
            }
        }
    }

    // ---- epilogue: emit fp16 h1
    int r0 = mBase + wid * 16 + g;
#pragma unroll
    for (int nt = 0; nt < 8; nt++) {
        int col = nt * 8 + t * 2;
        if (r0 < n)
            *(__half2*)&g_h1h[(size_t)r0 * HH + col] =
                __floats2half2_rn(acc[nt][0], acc[nt][1]);
        if (r0 + 8 < n)
            *(__half2*)&g_h1h[(size_t)(r0 + 8) * HH + col] =
                __floats2half2_rn(acc[nt][2], acc[nt][3]);
    }
}

// ---------------- layer-1 aggregate + bias + ReLU + @W2 ---------------------
// warp per dst; lane owns half2 slot 'lane'. Edge indices + weights staged
// lane-parallel in smem to break the col->dinv->row dependency chain.
__global__ __launch_bounds__(256) void k_agg1(const float* __restrict__ b1,
                                              const float* __restrict__ W2,
                                              int n) {
    __shared__ float b1s[HH];
    __shared__ float w2t[CC * HH];
    __shared__ int   sc[8][32];
    __shared__ float swt[8][32];

    int tid = threadIdx.x;
    if (tid < HH) b1s[tid] = b1[tid];
    for (int i = tid; i < CC * HH; i += 256) {
        int c = i >> 6, k = i & 63;
        w2t[i] = W2[k * CC + c];
    }
    __syncthreads();

    int warp = tid >> 5, lane = tid & 31;
    int d = blockIdx.x * 8 + warp;
    if (d >= n) return;

    float dd = g_dinv[d];
    const __half2* h2 = (const __half2*)g_h1h;

    float2 self = __half22float2(h2[(size_t)d * 32 + lane]);
    float2 acc;                            // = sum dinv[s]*h[s] + dd*h[d]
    acc.x = self.x * dd;
    acc.y = self.y * dd;

    int e0 = g_rowptr[d];
    int e1 = g_rowptr[d + 1];
    for (int base = e0; base < e1; base += 32) {
        int cnt = min(32, e1 - base);
        if (lane < cnt) {
            int s = g_col[base + lane];        // one coalesced load for 32 edges
            sc[warp][lane]  = s;
            swt[warp][lane] = g_dinv[s];       // one 32-lane gather
        }
        __syncwarp();
        int j = 0;
        for (; j + 4 <= cnt; j += 4) {
            int s0 = sc[warp][j],     s1 = sc[warp][j + 1];
            int s2 = sc[warp][j + 2], s3 = sc[warp][j + 3];
            float w0 = swt[warp][j],     w1 = swt[warp][j + 1];
            float w2 = swt[warp][j + 2], w3 = swt[warp][j + 3];
            float2 v0 = __half22float2(h2[(size_t)s0 * 32 + lane]);
            float2 v1 = __half22float2(h2[(size_t)s1 * 32 + lane]);
            float2 v2 = __half22float2(h2[(size_t)s2 * 32 + lane]);
            float2 v3 = __half22float2(h2[(size_t)s3 * 32 + lane]);
            acc.x += w0 * v0.x + w1 * v1.x + w2 * v2.x + w3 * v3.x;
            acc.y += w0 * v0.y + w1 * v1.y + w2 * v2.y + w3 * v3.y;
        }
        for (; j < cnt; j++) {
            int s = sc[warp][j];
            float w = swt[warp][j];
            float2 v = __half22float2(h2[(size_t)s * 32 + lane]);
            acc.x += w * v.x;
            acc.y += w * v.y;
        }
        __syncwarp();
    }

    float hx = fmaxf(dd * acc.x + b1s[2 * lane], 0.f);
    float hy = fmaxf(dd * acc.y + b1s[2 * lane + 1], 0.f);

    float pw[8];
#pragma unroll
    for (int c = 0; c < 8; c++) {
        float2 q = *(float2*)&w2t[c * HH + 2 * lane];
        pw[c] = hx * q.x + hy * q.y;
    }
#pragma unroll
    for (int c = 0; c < 8; c++) {
        pw[c] += __shfl_down_sync(0xffffffffu, pw[c], 16);
        pw[c] += __shfl_down_sync(0xffffffffu, pw[c], 8);
        pw[c] += __shfl_down_sync(0xffffffffu, pw[c], 4);
        pw[c] += __shfl_down_sync(0xffffffffu, pw[c], 2);
        pw[c] += __shfl_down_sync(0xffffffffu, pw[c], 1);
    }
    if (lane == 0) {
        // store t2' = dinv[d] * (relu(h) @ W2)  (pre-scaled for layer 2)
        *(float4*)&g_t2[(size_t)d * CC] =
            make_float4(dd * pw[0], dd * pw[1], dd * pw[2], dd * pw[3]);
        *(float4*)&g_t2[(size_t)d * CC + 4] =
            make_float4(dd * pw[4], dd * pw[5], dd * pw[6], dd * pw[7]);
    }
}

// ---------------- layer-2 aggregate + b2 -> out ------------------------------
// out[d] = dd * (sum_edges t2'[s] + t2'[d]) + b2 ; cols staged lane-parallel
// lane = j*8 + c; lane-j walks slots {j, j+4, j+8, ...} (stride 4, exhaustive)
__global__ __launch_bounds__(256) void k_agg2(const float* __restrict__ b2,
                                              float* __restrict__ out, int n) {
    __shared__ int sc[8][32];

    int tid  = threadIdx.x;
    int warp = tid >> 5, lane = tid & 31;
    int d = blockIdx.x * 8 + warp;
    if (d >= n) return;
    int j = lane >> 3, c = lane & 7;

    float dd  = g_dinv[d];
    int e0 = g_rowptr[d];
    int e1 = g_rowptr[d + 1];
    float acc = 0.f;
    for (int base = e0; base < e1; base += 32) {
        int cnt = min(32, e1 - base);
        if (lane < cnt) sc[warp][lane] = g_col[base + lane];
        __syncwarp();
        int q = j;
        for (; q + 8 <= cnt; q += 8) {
            int s0 = sc[warp][q];
            int s1 = sc[warp][q + 4];
            float u0 = g_t2[(size_t)s0 * CC + c];
            float u1 = g_t2[(size_t)s1 * CC + c];
            acc += u0 + u1;
        }
        for (; q < cnt; q += 4)                 // exhaustive stride-4 tail
            acc += g_t2[(size_t)sc[warp][q] * CC + c];
        __syncwarp();
    }
    acc += __shfl_down_sync(0xffffffffu, acc, 16);
    acc += __shfl_down_sync(0xffffffffu, acc, 8);
    if (j == 0) {
        float r = dd * (acc + g_t2[(size_t)d * CC + c]) + b2[c];
        out[(size_t)d * CC + c] = r;
    }
}

// ---------------- launch ------------------------------------------------------
extern "C" void kernel_launch(void* const* d_in, const int* in_sizes, int n_in,
                              void* d_out, int out_size) {
    const float* x  = (const float*)d_in[0];
    const int*   ei = (const int*)d_in[1];
    const float* W1 = (const float*)d_in[2];
    const float* b1 = (const float*)d_in[3];
    const float* W2 = (const float*)d_in[4];
    const float* b2 = (const float*)d_in[5];

    int n = in_sizes[0] / FIN;   // 100000
    int e = in_sizes[1] / 2;     // 3200000
    const int* src = ei;
    const int* dst = ei + e;

    int nb = (n + 255) / 256;

    cudaFuncSetAttribute(k_gemm1_mma, cudaFuncAttributeMaxDynamicSharedMemorySize,
                         SMEM_GEMM);

    void* degAddr = nullptr;
    cudaGetSymbolAddress(&degAddr, g_deg);

    if (g_s2) {
        // fork: GEMM path on g_s2, CSR path on main stream
        cudaEventRecord(g_evA, 0);
        cudaStreamWaitEvent(g_s2, g_evA, 0);
        k_prep_w1<<<(HH * FIN + 255) / 256, 256, 0, g_s2>>>(W1);
        k_gemm1_mma<<<(n + 127) / 128, 256, SMEM_GEMM, g_s2>>>(x, n);
        cudaEventRecord(g_evB, g_s2);

        cudaMemsetAsync(degAddr, 0, (size_t)n * sizeof(int), 0);
        k_hist<<<(e + 255) / 256, 256>>>(dst, e);
        k_bsum<<<nb, 256>>>(n);
        k_scan_bsum<<<1, 512>>>(nb);
        k_scan_final<<<nb, 256>>>(n, e);
        k_scatter<<<(e + 255) / 256, 256>>>(src, dst, e);

        cudaStreamWaitEvent(0, g_evB, 0);   // join
    } else {
        cudaMemsetAsync(degAddr, 0, (size_t)n * sizeof(int), 0);
        k_hist<<<(e + 255) / 256, 256>>>(dst, e);
        k_bsum<<<nb, 256>>>(n);
        k_scan_bsum<<<1, 512>>>(nb);
        k_scan_final<<<nb, 256>>>(n, e);
        k_scatter<<<(e + 255) / 256, 256>>>(src, dst, e);
        k_prep_w1<<<(HH * FIN + 255) / 256, 256>>>(W1);
        k_gemm1_mma<<<(n + 127) / 128, 256, SMEM_GEMM>>>(x, n);
    }

    k_agg1<<<(n + 7) / 8, 256>>>(b1, W2, n);
    k_agg2<<<(n + 7) / 8, 256>>>(b2, (float*)d_out, n);
}